// round 1
// baseline (speedup 1.0000x reference)
#include <cuda_runtime.h>

#define BB  8
#define N0  8192
#define NP  2048
#define CPf 512
#define CSf 256
#define C1f 256
#define C2f 256
#define KW  768   // CP+CS

// ---------------- scratch (device globals; no allocation) ----------------
__device__ int   g_idx[BB*N0*3];
__device__ float g_wt [BB*N0*3];
__device__ float g_Gt [BB*NP*C1f];     // [b][n][o]  (W1a @ feat_prev, transposed)
__device__ float g_y1 [BB*C1f*N0];     // layer-1 pre-BN
__device__ float g_z  [BB*C2f*N0];     // layer-2 pre-BN
__device__ float g_sc1[C1f], g_bi1[C1f], g_sc2[C2f], g_bi2[C2f];

// ---------------- kNN: 3 nearest of 2048 per query ----------------
__global__ void knn_kernel(const float* __restrict__ xyz,
                           const float* __restrict__ xyzp) {
    __shared__ float sx[NP], sy[NP], sz[NP], s2[NP];
    int b = blockIdx.y;
    const float* p = xyzp + (size_t)b*3*NP;
    for (int j = threadIdx.x; j < NP; j += blockDim.x) {
        float X = p[j], Y = p[NP + j], Z = p[2*NP + j];
        sx[j] = X; sy[j] = Y; sz[j] = Z; s2[j] = X*X + Y*Y + Z*Z;
    }
    __syncthreads();
    int n = blockIdx.x*blockDim.x + threadIdx.x;
    const float* q = xyz + (size_t)b*3*N0;
    float qx = q[n], qy = q[N0 + n], qz = q[2*N0 + n];
    float q2 = qx*qx + qy*qy + qz*qz;
    float d0 = 1e30f, d1 = 1e30f, d2 = 1e30f;
    int   i0 = 0, i1 = 0, i2 = 0;
#pragma unroll 4
    for (int j = 0; j < NP; ++j) {
        float dot = qx*sx[j] + qy*sy[j] + qz*sz[j];
        float d = (q2 + s2[j]) - 2.0f*dot;   // same expansion as reference
        if (d < d2) {
            if (d < d1) {
                d2 = d1; i2 = i1;
                if (d < d0) { d1 = d0; i1 = i0; d0 = d; i0 = j; }
                else        { d1 = d;  i1 = j; }
            } else { d2 = d; i2 = j; }
        }
    }
    float e0 = 1.0f/(fmaxf(d0, 1e-10f) + 1e-8f);
    float e1 = 1.0f/(fmaxf(d1, 1e-10f) + 1e-8f);
    float e2 = 1.0f/(fmaxf(d2, 1e-10f) + 1e-8f);
    float inv = 1.0f/(e0 + e1 + e2);
    size_t base = ((size_t)b*N0 + n)*3;
    g_idx[base]   = i0; g_idx[base+1] = i1; g_idx[base+2] = i2;
    g_wt [base]   = e0*inv; g_wt[base+1] = e1*inv; g_wt[base+2] = e2*inv;
}

// ---------------- GEMM 1a: Gt[b][n][o] = sum_c W1[o][c]*feat[b][c][n], c<512 --------
__global__ void gemm1a_kernel(const float* __restrict__ feat,
                              const float* __restrict__ W1) {
    __shared__ __align__(16) float As[16][64];   // [k][n]
    __shared__ __align__(16) float Ws[16][68];   // [k][o], padded
    int b = blockIdx.z;
    int nb = blockIdx.x*64, ob = blockIdx.y*64;
    const float* A = feat + (size_t)b*CPf*NP;
    int t = threadIdx.x, tx = t & 15, ty = t >> 4;
    float acc[4][4] = {};
    for (int k0 = 0; k0 < CPf; k0 += 16) {
#pragma unroll
        for (int qy = 0; qy < 4; qy++) {
            int i = t + qy*256;
            int kk = i >> 6, nn = i & 63;
            As[kk][nn] = A[(size_t)(k0 + kk)*NP + nb + nn];
        }
        {
            int oo = t >> 2, k4 = (t & 3)*4;
            float4 wv = *(const float4*)&W1[(size_t)(ob + oo)*KW + k0 + k4];
            Ws[k4  ][oo] = wv.x; Ws[k4+1][oo] = wv.y;
            Ws[k4+2][oo] = wv.z; Ws[k4+3][oo] = wv.w;
        }
        __syncthreads();
#pragma unroll
        for (int kk = 0; kk < 16; ++kk) {
            float4 av = *(const float4*)&As[kk][ty*4];
            float4 wv = *(const float4*)&Ws[kk][tx*4];
            float a[4] = {av.x, av.y, av.z, av.w};
            float w[4] = {wv.x, wv.y, wv.z, wv.w};
#pragma unroll
            for (int i = 0; i < 4; i++)
#pragma unroll
                for (int j = 0; j < 4; j++)
                    acc[i][j] = fmaf(a[i], w[j], acc[i][j]);
        }
        __syncthreads();
    }
    float* Ct = g_Gt + (size_t)b*NP*C1f;
#pragma unroll
    for (int i = 0; i < 4; i++) {
        float4 v = make_float4(acc[i][0], acc[i][1], acc[i][2], acc[i][3]);
        *(float4*)&Ct[(size_t)(nb + ty*4 + i)*C1f + ob + tx*4] = v;
    }
}

// -------- GEMM 1b + gather: y1[b][o][n] = W1b@skip + sum_k w*Gt[idx] --------
__global__ void gemm1b_kernel(const float* __restrict__ skip,
                              const float* __restrict__ W1) {
    __shared__ __align__(16) float As[16][64];
    __shared__ __align__(16) float Ws[16][68];
    __shared__ int   sid[192];
    __shared__ float swt[192];
    int b = blockIdx.z;
    int nb = blockIdx.x*64, ob = blockIdx.y*64;
    const float* A = skip + (size_t)b*CSf*N0;
    int t = threadIdx.x, tx = t & 15, ty = t >> 4;
    if (t < 192) {
        size_t base = ((size_t)b*N0 + nb)*3 + t;
        sid[t] = g_idx[base]; swt[t] = g_wt[base];
    }
    float acc[4][4] = {};
    for (int k0 = 0; k0 < CSf; k0 += 16) {
#pragma unroll
        for (int qy = 0; qy < 4; qy++) {
            int i = t + qy*256;
            int kk = i >> 6, nn = i & 63;
            As[kk][nn] = A[(size_t)(k0 + kk)*N0 + nb + nn];
        }
        {
            int oo = t >> 2, k4 = (t & 3)*4;
            float4 wv = *(const float4*)&W1[(size_t)(ob + oo)*KW + CPf + k0 + k4];
            Ws[k4  ][oo] = wv.x; Ws[k4+1][oo] = wv.y;
            Ws[k4+2][oo] = wv.z; Ws[k4+3][oo] = wv.w;
        }
        __syncthreads();
#pragma unroll
        for (int kk = 0; kk < 16; ++kk) {
            float4 av = *(const float4*)&As[kk][ty*4];
            float4 wv = *(const float4*)&Ws[kk][tx*4];
            float a[4] = {av.x, av.y, av.z, av.w};
            float w[4] = {wv.x, wv.y, wv.z, wv.w};
#pragma unroll
            for (int i = 0; i < 4; i++)
#pragma unroll
                for (int j = 0; j < 4; j++)
                    acc[i][j] = fmaf(a[i], w[j], acc[i][j]);
        }
        __syncthreads();
    }
    // gather epilogue: interpolation of Gt rows (L2-resident)
    const float* Gt = g_Gt + (size_t)b*NP*C1f;
#pragma unroll
    for (int i = 0; i < 4; i++) {
        int nn = ty*4 + i;
#pragma unroll
        for (int k = 0; k < 3; k++) {
            int   id = sid[nn*3 + k];
            float wk = swt[nn*3 + k];
            float4 gv = *(const float4*)&Gt[(size_t)id*C1f + ob + tx*4];
            acc[i][0] = fmaf(wk, gv.x, acc[i][0]);
            acc[i][1] = fmaf(wk, gv.y, acc[i][1]);
            acc[i][2] = fmaf(wk, gv.z, acc[i][2]);
            acc[i][3] = fmaf(wk, gv.w, acc[i][3]);
        }
    }
    float* Y = g_y1 + (size_t)b*C1f*N0;
#pragma unroll
    for (int j = 0; j < 4; j++) {
        float4 v = make_float4(acc[0][j], acc[1][j], acc[2][j], acc[3][j]);
        *(float4*)&Y[(size_t)(ob + tx*4 + j)*N0 + nb + ty*4] = v;
    }
}

// ---------------- BN stats (deterministic, one block per channel) ----------------
__global__ void stats_kernel(const float* __restrict__ gain,
                             const float* __restrict__ beta, int layer) {
    const float* y = layer ? g_z : g_y1;
    int o = blockIdx.x, t = threadIdx.x;
    float s = 0.f, s2 = 0.f;
    for (int b = 0; b < BB; b++) {
        const float* p = y + ((size_t)b*C1f + o)*N0;
        for (int n = t; n < N0; n += 256) {
            float v = p[n];
            s += v; s2 = fmaf(v, v, s2);
        }
    }
    __shared__ float r1[256], r2[256];
    r1[t] = s; r2[t] = s2; __syncthreads();
    for (int h = 128; h > 0; h >>= 1) {
        if (t < h) { r1[t] += r1[t+h]; r2[t] += r2[t+h]; }
        __syncthreads();
    }
    if (t == 0) {
        const float invN = 1.0f/((float)BB*N0);
        float m   = r1[0]*invN;
        float var = r2[0]*invN - m*m;
        float sc  = gain[o] * (1.0f/sqrtf(var + 1e-3f));
        if (layer) { g_sc2[o] = sc; g_bi2[o] = beta[o] - m*sc; }
        else       { g_sc1[o] = sc; g_bi1[o] = beta[o] - m*sc; }
    }
}

// ------- GEMM 2: z = W2 @ lrelu(BN1(y1)), BN applied on smem load -------
__global__ void gemm2_kernel(const float* __restrict__ W2) {
    __shared__ __align__(16) float As[16][64];
    __shared__ __align__(16) float Ws[16][68];
    int b = blockIdx.z;
    int nb = blockIdx.x*64, ob = blockIdx.y*64;
    const float* A = g_y1 + (size_t)b*C1f*N0;
    int t = threadIdx.x, tx = t & 15, ty = t >> 4;
    float acc[4][4] = {};
    for (int k0 = 0; k0 < C1f; k0 += 16) {
#pragma unroll
        for (int qy = 0; qy < 4; qy++) {
            int i = t + qy*256;
            int kk = i >> 6, nn = i & 63;
            float v = A[(size_t)(k0 + kk)*N0 + nb + nn];
            v = fmaf(v, g_sc1[k0 + kk], g_bi1[k0 + kk]);
            v = (v >= 0.f) ? v : 0.01f*v;
            As[kk][nn] = v;
        }
        {
            int oo = t >> 2, k4 = (t & 3)*4;
            float4 wv = *(const float4*)&W2[(size_t)(ob + oo)*C1f + k0 + k4];
            Ws[k4  ][oo] = wv.x; Ws[k4+1][oo] = wv.y;
            Ws[k4+2][oo] = wv.z; Ws[k4+3][oo] = wv.w;
        }
        __syncthreads();
#pragma unroll
        for (int kk = 0; kk < 16; ++kk) {
            float4 av = *(const float4*)&As[kk][ty*4];
            float4 wv = *(const float4*)&Ws[kk][tx*4];
            float a[4] = {av.x, av.y, av.z, av.w};
            float w[4] = {wv.x, wv.y, wv.z, wv.w};
#pragma unroll
            for (int i = 0; i < 4; i++)
#pragma unroll
                for (int j = 0; j < 4; j++)
                    acc[i][j] = fmaf(a[i], w[j], acc[i][j]);
        }
        __syncthreads();
    }
    float* Z = g_z + (size_t)b*C2f*N0;
#pragma unroll
    for (int j = 0; j < 4; j++) {
        float4 v = make_float4(acc[0][j], acc[1][j], acc[2][j], acc[3][j]);
        *(float4*)&Z[(size_t)(ob + tx*4 + j)*N0 + nb + ty*4] = v;
    }
}

// ---------------- output: lrelu(BN2(z)) ----------------
__global__ void out_kernel(float* __restrict__ out) {
    size_t i = (size_t)blockIdx.x*blockDim.x + threadIdx.x;   // float4 index
    const size_t total4 = (size_t)BB*C2f*N0/4;
    if (i >= total4) return;
    int ch = (int)((i/(N0/4)) % C2f);
    float sc = g_sc2[ch], bi = g_bi2[ch];
    float4 v = *((const float4*)g_z + i);
    v.x = fmaf(v.x, sc, bi); v.x = (v.x >= 0.f) ? v.x : 0.01f*v.x;
    v.y = fmaf(v.y, sc, bi); v.y = (v.y >= 0.f) ? v.y : 0.01f*v.y;
    v.z = fmaf(v.z, sc, bi); v.z = (v.z >= 0.f) ? v.z : 0.01f*v.z;
    v.w = fmaf(v.w, sc, bi); v.w = (v.w >= 0.f) ? v.w : 0.01f*v.w;
    *((float4*)out + i) = v;
}

// ---------------- launch ----------------
extern "C" void kernel_launch(void* const* d_in, const int* in_sizes, int n_in,
                              void* d_out, int out_size) {
    const float* xyz   = (const float*)d_in[0];
    const float* skip  = (const float*)d_in[1];
    const float* xyzp  = (const float*)d_in[2];
    const float* featp = (const float*)d_in[3];
    const float* W1    = (const float*)d_in[4];
    const float* g1    = (const float*)d_in[5];
    const float* b1    = (const float*)d_in[6];
    const float* W2    = (const float*)d_in[7];
    const float* g2    = (const float*)d_in[8];
    const float* b2    = (const float*)d_in[9];
    float* out = (float*)d_out;

    const size_t xyz_elems = (size_t)BB*3*N0;        // 196608
    const size_t nf_elems  = (size_t)BB*C2f*N0;      // 16777216
    size_t off = 0;
    if ((size_t)out_size >= xyz_elems + nf_elems) {
        // output is (xyz, nf) concatenated — copy xyz head through
        cudaMemcpyAsync(out, xyz, xyz_elems*sizeof(float),
                        cudaMemcpyDeviceToDevice);
        off = xyz_elems;
    }

    knn_kernel   <<<dim3(N0/256, BB),        256>>>(xyz, xyzp);
    gemm1a_kernel<<<dim3(NP/64,  C1f/64, BB), 256>>>(featp, W1);
    gemm1b_kernel<<<dim3(N0/64,  C1f/64, BB), 256>>>(skip, W1);
    stats_kernel <<<C1f, 256>>>(g1, b1, 0);
    gemm2_kernel <<<dim3(N0/64,  C2f/64, BB), 256>>>(W2);
    stats_kernel <<<C2f, 256>>>(g2, b2, 1);
    out_kernel   <<<(unsigned)((nf_elems/4 + 255)/256), 256>>>(out + off);
}

// round 2
// speedup vs baseline: 1.1565x; 1.1565x over previous
#include <cuda_runtime.h>

#define BB  8
#define N0  8192
#define NP  2048
#define CPf 512
#define CSf 256
#define C1f 256
#define C2f 256
#define KW  768   // CP+CS

typedef unsigned long long u64;

#define PACK2(r, lo, hi)   asm("mov.b64 %0, {%1, %2};" : "=l"(r) : "f"(lo), "f"(hi))
#define UNPACK2(lo, hi, v) asm("mov.b64 {%0, %1}, %2;" : "=f"(lo), "=f"(hi) : "l"(v))
#define FMA2(d, a, b)      asm("fma.rn.f32x2 %0, %1, %2, %3;" : "=l"(d) : "l"(a), "l"(b), "l"(d))

// ---------------- scratch (device globals; no allocation) ----------------
__device__ int   g_idx[BB*N0*3];
__device__ float g_wt [BB*N0*3];
__device__ float g_Gt [BB*NP*C1f];     // [b][n][o]  (W1a @ feat_prev, transposed)
__device__ float g_y1 [BB*C1f*N0];     // layer-1 pre-BN
__device__ float g_z  [BB*C2f*N0];     // layer-2 pre-BN
__device__ float g_p1 [C1f*512], g_p2[C1f*512];     // per-block stats partials
__device__ float g_sc1[C1f], g_bi1[C1f], g_sc2[C2f], g_bi2[C2f];

// ---------------- kNN: 3 nearest of 2048 per query ----------------
__global__ void knn_kernel(const float* __restrict__ xyz,
                           const float* __restrict__ xyzp) {
    __shared__ float4 sp[NP];          // (x,y,z,|p|^2) — 1 LDS.128 per point
    int b = blockIdx.y;
    const float* p = xyzp + (size_t)b*3*NP;
    for (int j = threadIdx.x; j < NP; j += blockDim.x) {
        float X = p[j], Y = p[NP + j], Z = p[2*NP + j];
        sp[j] = make_float4(X, Y, Z, X*X + Y*Y + Z*Z);
    }
    __syncthreads();
    int n = blockIdx.x*blockDim.x + threadIdx.x;
    const float* q = xyz + (size_t)b*3*N0;
    float qx = q[n], qy = q[N0 + n], qz = q[2*N0 + n];
    float q2 = qx*qx + qy*qy + qz*qz;
    float d0 = 1e30f, d1 = 1e30f, d2 = 1e30f;
    int   i0 = 0, i1 = 0, i2 = 0;
#pragma unroll 4
    for (int j = 0; j < NP; ++j) {
        float4 v = sp[j];
        float dot = qx*v.x + qy*v.y + qz*v.z;
        float d = (q2 + v.w) - 2.0f*dot;
        if (d < d2) {
            if (d < d1) {
                d2 = d1; i2 = i1;
                if (d < d0) { d1 = d0; i1 = i0; d0 = d; i0 = j; }
                else        { d1 = d;  i1 = j; }
            } else { d2 = d; i2 = j; }
        }
    }
    float e0 = 1.0f/(fmaxf(d0, 1e-10f) + 1e-8f);
    float e1 = 1.0f/(fmaxf(d1, 1e-10f) + 1e-8f);
    float e2 = 1.0f/(fmaxf(d2, 1e-10f) + 1e-8f);
    float inv = 1.0f/(e0 + e1 + e2);
    size_t base = ((size_t)b*N0 + n)*3;
    g_idx[base]   = i0; g_idx[base+1] = i1; g_idx[base+2] = i2;
    g_wt [base]   = e0*inv; g_wt[base+1] = e1*inv; g_wt[base+2] = e2*inv;
}

// =====================================================================
//  f32x2-packed 128x128 GEMM tile machinery (256 threads, 8x8/thread)
//  acc[j][i2]: j = channel (8), i2 = n-pair (4); pair = (n_even, n_odd)
// =====================================================================

// mainloop body (shared shape): As[16][128] (k x n), Ws[16][136] (k x o)
#define GEMM_COMPUTE(acc, As, Ws, tx, ty)                                   \
    _Pragma("unroll")                                                       \
    for (int kk = 0; kk < 16; ++kk) {                                       \
        ulonglong2 aA = *(const ulonglong2*)&As[kk][ty*8];                  \
        ulonglong2 aB = *(const ulonglong2*)&As[kk][ty*8 + 4];              \
        u64 ap0 = aA.x, ap1 = aA.y, ap2 = aB.x, ap3 = aB.y;                 \
        float4 w0 = *(const float4*)&Ws[kk][tx*8];                          \
        float4 w1 = *(const float4*)&Ws[kk][tx*8 + 4];                      \
        u64 wb[8];                                                          \
        PACK2(wb[0], w0.x, w0.x); PACK2(wb[1], w0.y, w0.y);                 \
        PACK2(wb[2], w0.z, w0.z); PACK2(wb[3], w0.w, w0.w);                 \
        PACK2(wb[4], w1.x, w1.x); PACK2(wb[5], w1.y, w1.y);                 \
        PACK2(wb[6], w1.z, w1.z); PACK2(wb[7], w1.w, w1.w);                 \
        _Pragma("unroll")                                                   \
        for (int j = 0; j < 8; ++j) {                                       \
            FMA2(acc[j][0], ap0, wb[j]);                                    \
            FMA2(acc[j][1], ap1, wb[j]);                                    \
            FMA2(acc[j][2], ap2, wb[j]);                                    \
            FMA2(acc[j][3], ap3, wb[j]);                                    \
        }                                                                   \
    }

// W staging: oo = t>>1, k8 = (t&1)*8 ; two float4 along k, transposed store
#define LOAD_W(Ws, Wsrc, ldw, ob, k0, t)                                    \
    {                                                                       \
        int oo = (t) >> 1, k8 = ((t) & 1) * 8;                              \
        const float* wp = (Wsrc) + (size_t)((ob) + oo)*(ldw) + (k0) + k8;   \
        float4 a = *(const float4*)wp;                                      \
        float4 c = *(const float4*)(wp + 4);                                \
        Ws[k8+0][oo] = a.x; Ws[k8+1][oo] = a.y;                             \
        Ws[k8+2][oo] = a.z; Ws[k8+3][oo] = a.w;                             \
        Ws[k8+4][oo] = c.x; Ws[k8+5][oo] = c.y;                             \
        Ws[k8+6][oo] = c.z; Ws[k8+7][oo] = c.w;                             \
    }

// ---------- GEMM 1a: Gt[b][n][o] = sum_c W1[o][c]*feat[b][c][n], c<512 ----------
__global__ __launch_bounds__(256, 2)
void gemm1a_kernel(const float* __restrict__ feat, const float* __restrict__ W1) {
    __shared__ __align__(16) float As[16][128];
    __shared__ __align__(16) float Ws[16][136];
    int b = blockIdx.z;
    int nb = blockIdx.x*128, ob = blockIdx.y*128;
    const float* A = feat + (size_t)b*CPf*NP;
    int t = threadIdx.x, tx = t & 15, ty = t >> 4;
    u64 acc[8][4] = {};
    for (int k0 = 0; k0 < CPf; k0 += 16) {
#pragma unroll
        for (int q = 0; q < 2; q++) {
            int idx = t + q*256;
            int kk = idx >> 5, nn = (idx & 31) << 2;
            *(float4*)&As[kk][nn] = *(const float4*)&A[(size_t)(k0+kk)*NP + nb + nn];
        }
        LOAD_W(Ws, W1, KW, ob, k0, t);
        __syncthreads();
        GEMM_COMPUTE(acc, As, Ws, tx, ty);
        __syncthreads();
    }
    float yv[8][8];
#pragma unroll
    for (int j = 0; j < 8; j++)
#pragma unroll
        for (int i2 = 0; i2 < 4; i2++)
            UNPACK2(yv[2*i2][j], yv[2*i2+1][j], acc[j][i2]);
    float* Ct = g_Gt + (size_t)b*NP*C1f;
#pragma unroll
    for (int i = 0; i < 8; i++) {
        float* dst = &Ct[(size_t)(nb + ty*8 + i)*C1f + ob + tx*8];
        *(float4*)dst       = make_float4(yv[i][0], yv[i][1], yv[i][2], yv[i][3]);
        *(float4*)(dst + 4) = make_float4(yv[i][4], yv[i][5], yv[i][6], yv[i][7]);
    }
}

// ---- GEMM 1b + gather + stats: y1 = W1b@skip + interp(Gt); partial BN stats ----
__global__ __launch_bounds__(256, 2)
void gemm1b_kernel(const float* __restrict__ skip, const float* __restrict__ W1) {
    __shared__ __align__(16) float As[16][128];
    __shared__ __align__(16) float Ws[16][136];
    __shared__ int   sid[384];
    __shared__ float swt[384];
    int b = blockIdx.z;
    int nb = blockIdx.x*128, ob = blockIdx.y*128;
    const float* A = skip + (size_t)b*CSf*N0;
    int t = threadIdx.x, tx = t & 15, ty = t >> 4;
    for (int i = t; i < 384; i += 256) {
        size_t base = ((size_t)b*N0 + nb)*3 + i;
        sid[i] = g_idx[base]; swt[i] = g_wt[base];
    }
    u64 acc[8][4] = {};
    for (int k0 = 0; k0 < CSf; k0 += 16) {
#pragma unroll
        for (int q = 0; q < 2; q++) {
            int idx = t + q*256;
            int kk = idx >> 5, nn = (idx & 31) << 2;
            *(float4*)&As[kk][nn] = *(const float4*)&A[(size_t)(k0+kk)*N0 + nb + nn];
        }
        LOAD_W(Ws, W1, KW, ob, CPf + k0, t);
        __syncthreads();
        GEMM_COMPUTE(acc, As, Ws, tx, ty);
        __syncthreads();
    }
    float yv[8][8];
#pragma unroll
    for (int j = 0; j < 8; j++)
#pragma unroll
        for (int i2 = 0; i2 < 4; i2++)
            UNPACK2(yv[2*i2][j], yv[2*i2+1][j], acc[j][i2]);
    // gather epilogue: + sum_k w * Gt[idx][o]
    const float* Gt = g_Gt + (size_t)b*NP*C1f;
#pragma unroll
    for (int i = 0; i < 8; i++) {
        int nn = ty*8 + i;
#pragma unroll
        for (int k = 0; k < 3; k++) {
            int   id = sid[nn*3 + k];
            float wk = swt[nn*3 + k];
            const float* gp = &Gt[(size_t)id*C1f + ob + tx*8];
            float4 g0 = *(const float4*)gp;
            float4 g1 = *(const float4*)(gp + 4);
            yv[i][0] = fmaf(wk, g0.x, yv[i][0]); yv[i][1] = fmaf(wk, g0.y, yv[i][1]);
            yv[i][2] = fmaf(wk, g0.z, yv[i][2]); yv[i][3] = fmaf(wk, g0.w, yv[i][3]);
            yv[i][4] = fmaf(wk, g1.x, yv[i][4]); yv[i][5] = fmaf(wk, g1.y, yv[i][5]);
            yv[i][6] = fmaf(wk, g1.z, yv[i][6]); yv[i][7] = fmaf(wk, g1.w, yv[i][7]);
        }
    }
    // fused BN stats partials (per 128-channel block slice)
    float* rs = &As[0][0];   // 2048 floats
    float* rq = &Ws[0][0];
#pragma unroll
    for (int j = 0; j < 8; j++) {
        float s = 0.f, s2 = 0.f;
#pragma unroll
        for (int i = 0; i < 8; i++) { s += yv[i][j]; s2 = fmaf(yv[i][j], yv[i][j], s2); }
        rs[ty*128 + tx*8 + j] = s;
        rq[ty*128 + tx*8 + j] = s2;
    }
    __syncthreads();
    if (t < 128) {
        float a = 0.f, c = 0.f;
#pragma unroll
        for (int r = 0; r < 16; r++) { a += rs[r*128 + t]; c += rq[r*128 + t]; }
        int pidx = blockIdx.x + 64*blockIdx.z;
        g_p1[(size_t)(ob + t)*512 + pidx] = a;
        g_p2[(size_t)(ob + t)*512 + pidx] = c;
    }
    float* Y = g_y1 + (size_t)b*C1f*N0;
#pragma unroll
    for (int j = 0; j < 8; j++) {
        float* dst = &Y[(size_t)(ob + tx*8 + j)*N0 + nb + ty*8];
        *(float4*)dst       = make_float4(yv[0][j], yv[1][j], yv[2][j], yv[3][j]);
        *(float4*)(dst + 4) = make_float4(yv[4][j], yv[5][j], yv[6][j], yv[7][j]);
    }
}

// ---------------- stats reduce: 512 partials -> scale/bias ----------------
__global__ void stats_reduce(const float* __restrict__ gain,
                             const float* __restrict__ beta, int layer) {
    int o = blockIdx.x, t = threadIdx.x;   // 128 threads
    const float* p1 = &g_p1[(size_t)o*512];
    const float* p2 = &g_p2[(size_t)o*512];
    float a = p1[t] + p1[t+128] + p1[t+256] + p1[t+384];
    float c = p2[t] + p2[t+128] + p2[t+256] + p2[t+384];
    __shared__ float r1[128], r2[128];
    r1[t] = a; r2[t] = c; __syncthreads();
    for (int h = 64; h > 0; h >>= 1) {
        if (t < h) { r1[t] += r1[t+h]; r2[t] += r2[t+h]; }
        __syncthreads();
    }
    if (t == 0) {
        const float invN = 1.0f/((float)BB*N0);
        float m   = r1[0]*invN;
        float var = r2[0]*invN - m*m;
        float sc  = gain[o] * (1.0f/sqrtf(var + 1e-3f));
        if (layer) { g_sc2[o] = sc; g_bi2[o] = beta[o] - m*sc; }
        else       { g_sc1[o] = sc; g_bi1[o] = beta[o] - m*sc; }
    }
}

// ------- GEMM 2: z = W2 @ lrelu(BN1(y1)); BN applied on smem stage; stats fused -------
__global__ __launch_bounds__(256, 2)
void gemm2_kernel(const float* __restrict__ W2) {
    __shared__ __align__(16) float As[16][128];
    __shared__ __align__(16) float Ws[16][136];
    int b = blockIdx.z;
    int nb = blockIdx.x*128, ob = blockIdx.y*128;
    const float* A = g_y1 + (size_t)b*C1f*N0;
    int t = threadIdx.x, tx = t & 15, ty = t >> 4;
    u64 acc[8][4] = {};
    for (int k0 = 0; k0 < C1f; k0 += 16) {
#pragma unroll
        for (int q = 0; q < 2; q++) {
            int idx = t + q*256;
            int kk = idx >> 5, nn = (idx & 31) << 2;
            float sc = g_sc1[k0 + kk], bi = g_bi1[k0 + kk];
            float4 v = *(const float4*)&A[(size_t)(k0+kk)*N0 + nb + nn];
            v.x = fmaf(v.x, sc, bi); v.x = (v.x >= 0.f) ? v.x : 0.01f*v.x;
            v.y = fmaf(v.y, sc, bi); v.y = (v.y >= 0.f) ? v.y : 0.01f*v.y;
            v.z = fmaf(v.z, sc, bi); v.z = (v.z >= 0.f) ? v.z : 0.01f*v.z;
            v.w = fmaf(v.w, sc, bi); v.w = (v.w >= 0.f) ? v.w : 0.01f*v.w;
            *(float4*)&As[kk][nn] = v;
        }
        LOAD_W(Ws, W2, C1f, ob, k0, t);
        __syncthreads();
        GEMM_COMPUTE(acc, As, Ws, tx, ty);
        __syncthreads();
    }
    float yv[8][8];
#pragma unroll
    for (int j = 0; j < 8; j++)
#pragma unroll
        for (int i2 = 0; i2 < 4; i2++)
            UNPACK2(yv[2*i2][j], yv[2*i2+1][j], acc[j][i2]);
    // fused BN stats partials
    float* rs = &As[0][0];
    float* rq = &Ws[0][0];
#pragma unroll
    for (int j = 0; j < 8; j++) {
        float s = 0.f, s2 = 0.f;
#pragma unroll
        for (int i = 0; i < 8; i++) { s += yv[i][j]; s2 = fmaf(yv[i][j], yv[i][j], s2); }
        rs[ty*128 + tx*8 + j] = s;
        rq[ty*128 + tx*8 + j] = s2;
    }
    __syncthreads();
    if (t < 128) {
        float a = 0.f, c = 0.f;
#pragma unroll
        for (int r = 0; r < 16; r++) { a += rs[r*128 + t]; c += rq[r*128 + t]; }
        int pidx = blockIdx.x + 64*blockIdx.z;
        g_p1[(size_t)(ob + t)*512 + pidx] = a;
        g_p2[(size_t)(ob + t)*512 + pidx] = c;
    }
    float* Z = g_z + (size_t)b*C2f*N0;
#pragma unroll
    for (int j = 0; j < 8; j++) {
        float* dst = &Z[(size_t)(ob + tx*8 + j)*N0 + nb + ty*8];
        *(float4*)dst       = make_float4(yv[0][j], yv[1][j], yv[2][j], yv[3][j]);
        *(float4*)(dst + 4) = make_float4(yv[4][j], yv[5][j], yv[6][j], yv[7][j]);
    }
}

// ---------------- output: lrelu(BN2(z)) ----------------
__global__ void out_kernel(float* __restrict__ out) {
    size_t i = (size_t)blockIdx.x*blockDim.x + threadIdx.x;   // float4 index
    const size_t total4 = (size_t)BB*C2f*N0/4;
    if (i >= total4) return;
    int ch = (int)((i/(N0/4)) % C2f);
    float sc = g_sc2[ch], bi = g_bi2[ch];
    float4 v = *((const float4*)g_z + i);
    v.x = fmaf(v.x, sc, bi); v.x = (v.x >= 0.f) ? v.x : 0.01f*v.x;
    v.y = fmaf(v.y, sc, bi); v.y = (v.y >= 0.f) ? v.y : 0.01f*v.y;
    v.z = fmaf(v.z, sc, bi); v.z = (v.z >= 0.f) ? v.z : 0.01f*v.z;
    v.w = fmaf(v.w, sc, bi); v.w = (v.w >= 0.f) ? v.w : 0.01f*v.w;
    *((float4*)out + i) = v;
}

// ---------------- launch ----------------
extern "C" void kernel_launch(void* const* d_in, const int* in_sizes, int n_in,
                              void* d_out, int out_size) {
    const float* xyz   = (const float*)d_in[0];
    const float* skip  = (const float*)d_in[1];
    const float* xyzp  = (const float*)d_in[2];
    const float* featp = (const float*)d_in[3];
    const float* W1    = (const float*)d_in[4];
    const float* g1    = (const float*)d_in[5];
    const float* b1    = (const float*)d_in[6];
    const float* W2    = (const float*)d_in[7];
    const float* g2    = (const float*)d_in[8];
    const float* b2    = (const float*)d_in[9];
    float* out = (float*)d_out;

    const size_t xyz_elems = (size_t)BB*3*N0;
    const size_t nf_elems  = (size_t)BB*C2f*N0;
    size_t off = 0;
    if ((size_t)out_size >= xyz_elems + nf_elems) {
        cudaMemcpyAsync(out, xyz, xyz_elems*sizeof(float),
                        cudaMemcpyDeviceToDevice);
        off = xyz_elems;
    }

    knn_kernel   <<<dim3(N0/256, BB),          256>>>(xyz, xyzp);
    gemm1a_kernel<<<dim3(NP/128,  C1f/128, BB), 256>>>(featp, W1);
    gemm1b_kernel<<<dim3(N0/128,  C1f/128, BB), 256>>>(skip, W1);
    stats_reduce <<<C1f, 128>>>(g1, b1, 0);
    gemm2_kernel <<<dim3(N0/128,  C2f/128, BB), 256>>>(W2);
    stats_reduce <<<C2f, 128>>>(g2, b2, 1);
    out_kernel   <<<(unsigned)((nf_elems/4 + 255)/256), 256>>>(out + off);
}

// round 4
// speedup vs baseline: 1.4336x; 1.2396x over previous
#include <cuda_runtime.h>
#include <cuda_bf16.h>
#include <cstdint>

#define BB  8
#define N0  8192
#define NP  2048
#define CPf 512
#define CSf 256
#define C1f 256
#define C2f 256
#define KW  768   // CP+CS

#define PITCH 144           // bytes per smem row: 32 bf16 hi (64B) | 32 bf16 lo (64B) | pad 16B
#define O_AS   0            // A tile: 128 rows x PITCH
#define O_BS   18432        // B tile: 128 rows x PITCH
// epilogue overlays (after mainloop):
#define O_SBUF 0            // 32 x 132 floats = 16896 B (inside As)
#define O_SID  16896        // 384 int
#define O_SWT  18432        // 384 float (inside Bs)
#define O_CHS  19968        // 128 float
#define O_CHQ  20480        // 128 float
#define SM_BYTES 36864

// ---------------- scratch (device globals) ----------------
__device__ int   g_idx[BB*N0*3];
__device__ float g_wt [BB*N0*3];
__device__ float g_Gt [BB*NP*C1f];
__device__ float g_y1 [BB*C1f*N0];
__device__ float g_z  [BB*C2f*N0];
__device__ float g_p1 [C1f*512], g_p2[C1f*512];
__device__ float g_sc1[C1f], g_bi1[C1f], g_sc2[C2f], g_bi2[C2f];

// ---------------- PTX wrappers (baseline ISA, compute_103-safe) ----------------
__device__ __forceinline__ uint32_t smem_u32(const void* p) {
    uint32_t a;
    asm("{ .reg .u64 t; cvta.to.shared.u64 t, %1; cvt.u32.u64 %0, t; }" : "=r"(a) : "l"(p));
    return a;
}
__device__ __forceinline__ void ldm4(uint32_t* r, uint32_t addr) {
    asm volatile("ldmatrix.sync.aligned.m8n8.x4.shared.b16 {%0,%1,%2,%3}, [%4];"
        : "=r"(r[0]), "=r"(r[1]), "=r"(r[2]), "=r"(r[3]) : "r"(addr));
}
__device__ __forceinline__ void mma_bf16(float* d, const uint32_t* a, const uint32_t* b) {
    asm volatile("mma.sync.aligned.m16n8k16.row.col.f32.bf16.bf16.f32 "
        "{%0,%1,%2,%3}, {%4,%5,%6,%7}, {%8,%9}, {%0,%1,%2,%3};"
        : "+f"(d[0]), "+f"(d[1]), "+f"(d[2]), "+f"(d[3])
        : "r"(a[0]), "r"(a[1]), "r"(a[2]), "r"(a[3]), "r"(b[0]), "r"(b[1]));
}
__device__ __forceinline__ uint32_t pack_bf16(float a, float b) {
    __nv_bfloat162 p = __floats2bfloat162_rn(a, b);   // .x = a (low), .y = b (high)
    return *(uint32_t*)&p;
}

// ---------------- kNN ----------------
__global__ void knn_kernel(const float* __restrict__ xyz,
                           const float* __restrict__ xyzp) {
    __shared__ float4 sp[NP];
    int b = blockIdx.y;
    const float* p = xyzp + (size_t)b*3*NP;
    for (int j = threadIdx.x; j < NP; j += blockDim.x) {
        float X = p[j], Y = p[NP + j], Z = p[2*NP + j];
        sp[j] = make_float4(X, Y, Z, X*X + Y*Y + Z*Z);
    }
    __syncthreads();
    int n = blockIdx.x*blockDim.x + threadIdx.x;
    const float* q = xyz + (size_t)b*3*N0;
    float qx = q[n], qy = q[N0 + n], qz = q[2*N0 + n];
    float q2 = qx*qx + qy*qy + qz*qz;
    float d0 = 1e30f, d1 = 1e30f, d2 = 1e30f;
    int   i0 = 0, i1 = 0, i2 = 0;
#pragma unroll 4
    for (int j = 0; j < NP; ++j) {
        float4 v = sp[j];
        float dot = qx*v.x + qy*v.y + qz*v.z;
        float d = (q2 + v.w) - 2.0f*dot;
        if (d < d2) {
            if (d < d1) {
                d2 = d1; i2 = i1;
                if (d < d0) { d1 = d0; i1 = i0; d0 = d; i0 = j; }
                else        { d1 = d;  i1 = j; }
            } else { d2 = d; i2 = j; }
        }
    }
    float e0 = 1.0f/(fmaxf(d0, 1e-10f) + 1e-8f);
    float e1 = 1.0f/(fmaxf(d1, 1e-10f) + 1e-8f);
    float e2 = 1.0f/(fmaxf(d2, 1e-10f) + 1e-8f);
    float inv = 1.0f/(e0 + e1 + e2);
    size_t base = ((size_t)b*N0 + n)*3;
    g_idx[base]   = i0; g_idx[base+1] = i1; g_idx[base+2] = i2;
    g_wt [base]   = e0*inv; g_wt[base+1] = e1*inv; g_wt[base+2] = e2*inv;
}

// ===================== bf16x3 mma.sync GEMM core =====================
// 512 threads, 16 warps (4 n-slices x 4 o-slices), CTA tile 128n x 128o, K chunk 32.
// acc[mt][nt][4]: warp tile 32n x 32o -> 2 m16 x 4 n8 mma tiles.
template<bool BN>
__device__ __forceinline__ void gemm_core(char* sm, uint32_t sb,
    const float* __restrict__ A, int ldn, int nb, int kA0,
    const float* __restrict__ W, int ldw, int ob, int kW0,
    int nk32, float acc[2][4][4])
{
    int t = threadIdx.x, lane = t & 31, wid = t >> 5;
    int wn = wid & 3, wo = wid >> 2;
    int rs = t & 127, cq = t >> 7;          // staging: row (n or o), k-quad (8 k's)
    uint32_t aAddr = sb + (uint32_t)(O_AS + (wn*32 + (lane & 15))*PITCH + ((lane >> 4) & 1)*16);
    uint32_t bAddr = sb + (uint32_t)(O_BS + (wo*32 + (lane & 7) + ((lane >> 4) & 1)*8)*PITCH
                                     + ((lane >> 3) & 1)*16);
    for (int it = 0; it < nk32; it++) {
        __syncthreads();
        // ---- stage A chunk: A[kA0+it*32 .. +31][nb..nb+127] -> [n][k] bf16 hi|lo ----
        {
            int kA = kA0 + it*32 + cq*8;
            const float* ap = A + (size_t)kA*ldn + nb + rs;
            float x[8];
#pragma unroll
            for (int j = 0; j < 8; j++) x[j] = ap[(size_t)j*ldn];
            if (BN) {
#pragma unroll
                for (int j = 0; j < 8; j++) {
                    float v = fmaf(x[j], g_sc1[kA + j], g_bi1[kA + j]);
                    x[j] = (v >= 0.f) ? v : 0.01f*v;
                }
            }
            float lo[8];
#pragma unroll
            for (int j = 0; j < 8; j++) {
                __nv_bfloat16 h = __float2bfloat16(x[j]);
                lo[j] = x[j] - __bfloat162float(h);
            }
            uint4 hw = make_uint4(pack_bf16(x[0], x[1]), pack_bf16(x[2], x[3]),
                                  pack_bf16(x[4], x[5]), pack_bf16(x[6], x[7]));
            uint4 lw = make_uint4(pack_bf16(lo[0], lo[1]), pack_bf16(lo[2], lo[3]),
                                  pack_bf16(lo[4], lo[5]), pack_bf16(lo[6], lo[7]));
            *(uint4*)(sm + O_AS + rs*PITCH + cq*16)      = hw;
            *(uint4*)(sm + O_AS + rs*PITCH + 64 + cq*16) = lw;
        }
        // ---- stage B chunk: W[ob+o][kW0+it*32 ..] -> [o][k] bf16 hi|lo ----
        {
            const float* wp = W + (size_t)(ob + rs)*ldw + kW0 + it*32 + cq*8;
            float4 v0 = *(const float4*)wp;
            float4 v1 = *(const float4*)(wp + 4);
            float x[8] = {v0.x, v0.y, v0.z, v0.w, v1.x, v1.y, v1.z, v1.w};
            float lo[8];
#pragma unroll
            for (int j = 0; j < 8; j++) {
                __nv_bfloat16 h = __float2bfloat16(x[j]);
                lo[j] = x[j] - __bfloat162float(h);
            }
            uint4 hw = make_uint4(pack_bf16(x[0], x[1]), pack_bf16(x[2], x[3]),
                                  pack_bf16(x[4], x[5]), pack_bf16(x[6], x[7]));
            uint4 lw = make_uint4(pack_bf16(lo[0], lo[1]), pack_bf16(lo[2], lo[3]),
                                  pack_bf16(lo[4], lo[5]), pack_bf16(lo[6], lo[7]));
            *(uint4*)(sm + O_BS + rs*PITCH + cq*16)      = hw;
            *(uint4*)(sm + O_BS + rs*PITCH + 64 + cq*16) = lw;
        }
        __syncthreads();
        // ---- 2 k16 steps: ldmatrix + 24 mma each ----
#pragma unroll
        for (int s16 = 0; s16 < 2; s16++) {
            uint32_t Ah[2][4], Al[2][4], Bh[2][4], Bl[2][4];
#pragma unroll
            for (int mt = 0; mt < 2; mt++) {
                uint32_t ad = aAddr + mt*16*PITCH + s16*32;
                ldm4(Ah[mt], ad); ldm4(Al[mt], ad + 64);
            }
#pragma unroll
            for (int np = 0; np < 2; np++) {
                uint32_t bd = bAddr + np*16*PITCH + s16*32;
                ldm4(Bh[np], bd); ldm4(Bl[np], bd + 64);
            }
#pragma unroll
            for (int mt = 0; mt < 2; mt++)
#pragma unroll
            for (int nt = 0; nt < 4; nt++) {
                const uint32_t* bh = &Bh[nt >> 1][(nt & 1)*2];
                const uint32_t* bl = &Bl[nt >> 1][(nt & 1)*2];
                mma_bf16(acc[mt][nt], Ah[mt], bh);
                mma_bf16(acc[mt][nt], Ah[mt], bl);
                mma_bf16(acc[mt][nt], Al[mt], bh);
            }
        }
    }
    __syncthreads();
}

// dump one 32-o strip of accumulators into sbuf[o_local][n] (conflict-free)
__device__ __forceinline__ void dump_strip(float* sbuf, int s, float acc[2][4][4]) {
    int t = threadIdx.x, lane = t & 31, wid = t >> 5;
    int wn = wid & 3, wo = wid >> 2;
    if (wo != s) return;
    int g = lane >> 2, c2 = (lane & 3)*2;
#pragma unroll
    for (int mt = 0; mt < 2; mt++)
#pragma unroll
    for (int nt = 0; nt < 4; nt++) {
        int nl = wn*32 + mt*16 + g;
        int ol = nt*8 + c2;
        sbuf[ol*132 + nl]       = acc[mt][nt][0];
        sbuf[(ol+1)*132 + nl]   = acc[mt][nt][1];
        sbuf[ol*132 + nl + 8]   = acc[mt][nt][2];
        sbuf[(ol+1)*132 + nl + 8] = acc[mt][nt][3];
    }
}

// ---------- GEMM 1a: Gt[b][n][o] = W1[:, :512] @ feat ----------
__global__ __launch_bounds__(512, 1)
void gemm1a_kernel(const float* __restrict__ feat, const float* __restrict__ W1) {
    static __shared__ __align__(16) char sm[SM_BYTES];
    uint32_t sb = smem_u32(sm);
    int b = blockIdx.z, nb = blockIdx.x*128, ob = blockIdx.y*128;
    int t = threadIdx.x;
    float acc[2][4][4] = {};
    gemm_core<false>(sm, sb, feat + (size_t)b*CPf*NP, NP, nb, 0,
                     W1, KW, ob, 0, CPf/32, acc);
    float* sbuf = (float*)(sm + O_SBUF);
    int n = t & 127, oq = t >> 7;
    for (int s = 0; s < 4; s++) {
        __syncthreads();
        dump_strip(sbuf, s, acc);
        __syncthreads();
        float f[8];
#pragma unroll
        for (int j = 0; j < 8; j++) f[j] = sbuf[(oq*8 + j)*132 + n];
        float* dst = &g_Gt[((size_t)b*NP + nb + n)*C1f + ob + s*32 + oq*8];
        *(float4*)dst       = make_float4(f[0], f[1], f[2], f[3]);
        *(float4*)(dst + 4) = make_float4(f[4], f[5], f[6], f[7]);
    }
}

// shared epilogue for 1b/2: optional gather, transpose writeout [o][n], BN-stat partials
__device__ __forceinline__ void epi_write(char* sm, float acc[2][4][4],
                                          float* __restrict__ Y, int nb, int ob,
                                          int b, bool gather) {
    int t = threadIdx.x;
    float* sbuf = (float*)(sm + O_SBUF);
    int*   sid  = (int*)(sm + O_SID);
    float* swt  = (float*)(sm + O_SWT);
    float* chs  = (float*)(sm + O_CHS);
    float* chq  = (float*)(sm + O_CHQ);
    if (gather) {
        for (int i = t; i < 384; i += 512) {
            size_t base = ((size_t)b*N0 + nb)*3 + i;
            sid[i] = g_idx[base]; swt[i] = g_wt[base];
        }
    }
    const float* Gt = g_Gt + (size_t)b*NP*C1f;
    for (int s = 0; s < 4; s++) {
        __syncthreads();
        dump_strip(sbuf, s, acc);
        __syncthreads();
        if (gather) {
            int n = t & 127, oq = t >> 7;
            float v[8];
#pragma unroll
            for (int j = 0; j < 8; j++) v[j] = sbuf[(oq*8 + j)*132 + n];
#pragma unroll
            for (int k = 0; k < 3; k++) {
                int   id = sid[n*3 + k];
                float wk = swt[n*3 + k];
                const float* gp = &Gt[(size_t)id*C1f + ob + s*32 + oq*8];
                float4 g0 = *(const float4*)gp;
                float4 g1 = *(const float4*)(gp + 4);
                v[0] = fmaf(wk, g0.x, v[0]); v[1] = fmaf(wk, g0.y, v[1]);
                v[2] = fmaf(wk, g0.z, v[2]); v[3] = fmaf(wk, g0.w, v[3]);
                v[4] = fmaf(wk, g1.x, v[4]); v[5] = fmaf(wk, g1.y, v[5]);
                v[6] = fmaf(wk, g1.z, v[6]); v[7] = fmaf(wk, g1.w, v[7]);
            }
#pragma unroll
            for (int j = 0; j < 8; j++) sbuf[(oq*8 + j)*132 + n] = v[j];
            __syncthreads();
        }
        {
            int ol = t >> 4, seg = t & 15, n = seg*8;
            const float* srow = &sbuf[ol*132 + n];
            float4 x0 = *(const float4*)srow;
            float4 x1 = *(const float4*)(srow + 4);
            float s1 = x0.x + x0.y + x0.z + x0.w + x1.x + x1.y + x1.z + x1.w;
            float s2 = 0.f;
            s2 = fmaf(x0.x, x0.x, s2); s2 = fmaf(x0.y, x0.y, s2);
            s2 = fmaf(x0.z, x0.z, s2); s2 = fmaf(x0.w, x0.w, s2);
            s2 = fmaf(x1.x, x1.x, s2); s2 = fmaf(x1.y, x1.y, s2);
            s2 = fmaf(x1.z, x1.z, s2); s2 = fmaf(x1.w, x1.w, s2);
            float* dst = &Y[(size_t)(ob + s*32 + ol)*N0 + nb + n];
            *(float4*)dst       = x0;
            *(float4*)(dst + 4) = x1;
#pragma unroll
            for (int off = 8; off; off >>= 1) {
                s1 += __shfl_down_sync(0xffffffffu, s1, off, 16);
                s2 += __shfl_down_sync(0xffffffffu, s2, off, 16);
            }
            if (seg == 0) { chs[s*32 + ol] = s1; chq[s*32 + ol] = s2; }
        }
    }
    __syncthreads();
    if (t < 128) {
        int pidx = blockIdx.x + 64*blockIdx.z;
        g_p1[(size_t)(ob + t)*512 + pidx] = chs[t];
        g_p2[(size_t)(ob + t)*512 + pidx] = chq[t];
    }
}

// ---- GEMM 1b: y1 = W1[:, 512:] @ skip + interp(Gt); fused stats ----
__global__ __launch_bounds__(512, 1)
void gemm1b_kernel(const float* __restrict__ skip, const float* __restrict__ W1) {
    static __shared__ __align__(16) char sm[SM_BYTES];
    uint32_t sb = smem_u32(sm);
    int b = blockIdx.z, nb = blockIdx.x*128, ob = blockIdx.y*128;
    float acc[2][4][4] = {};
    gemm_core<false>(sm, sb, skip + (size_t)b*CSf*N0, N0, nb, 0,
                     W1, KW, ob, CPf, CSf/32, acc);
    epi_write(sm, acc, g_y1 + (size_t)b*C1f*N0, nb, ob, b, true);
}

// ---- GEMM 2: z = W2 @ lrelu(BN1(y1)); BN on A-stage; fused stats ----
__global__ __launch_bounds__(512, 1)
void gemm2_kernel(const float* __restrict__ W2) {
    static __shared__ __align__(16) char sm[SM_BYTES];
    uint32_t sb = smem_u32(sm);
    int b = blockIdx.z, nb = blockIdx.x*128, ob = blockIdx.y*128;
    float acc[2][4][4] = {};
    gemm_core<true>(sm, sb, g_y1 + (size_t)b*C1f*N0, N0, nb, 0,
                    W2, C1f, ob, 0, C1f/32, acc);
    epi_write(sm, acc, g_z + (size_t)b*C2f*N0, nb, ob, b, false);
}

// ---------------- stats reduce ----------------
__global__ void stats_reduce(const float* __restrict__ gain,
                             const float* __restrict__ beta, int layer) {
    int o = blockIdx.x, t = threadIdx.x;
    const float* p1 = &g_p1[(size_t)o*512];
    const float* p2 = &g_p2[(size_t)o*512];
    float a = p1[t] + p1[t+128] + p1[t+256] + p1[t+384];
    float c = p2[t] + p2[t+128] + p2[t+256] + p2[t+384];
    __shared__ float r1[128], r2[128];
    r1[t] = a; r2[t] = c; __syncthreads();
    for (int h = 64; h > 0; h >>= 1) {
        if (t < h) { r1[t] += r1[t+h]; r2[t] += r2[t+h]; }
        __syncthreads();
    }
    if (t == 0) {
        const float invN = 1.0f/((float)BB*N0);
        float m   = r1[0]*invN;
        float var = r2[0]*invN - m*m;
        float sc  = gain[o] * (1.0f/sqrtf(var + 1e-3f));
        if (layer) { g_sc2[o] = sc; g_bi2[o] = beta[o] - m*sc; }
        else       { g_sc1[o] = sc; g_bi1[o] = beta[o] - m*sc; }
    }
}

// ---------------- output: lrelu(BN2(z)) ----------------
__global__ void out_kernel(float* __restrict__ out) {
    size_t i = (size_t)blockIdx.x*blockDim.x + threadIdx.x;
    const size_t total4 = (size_t)BB*C2f*N0/4;
    if (i >= total4) return;
    int ch = (int)((i/(N0/4)) % C2f);
    float sc = g_sc2[ch], bi = g_bi2[ch];
    float4 v = *((const float4*)g_z + i);
    v.x = fmaf(v.x, sc, bi); v.x = (v.x >= 0.f) ? v.x : 0.01f*v.x;
    v.y = fmaf(v.y, sc, bi); v.y = (v.y >= 0.f) ? v.y : 0.01f*v.y;
    v.z = fmaf(v.z, sc, bi); v.z = (v.z >= 0.f) ? v.z : 0.01f*v.z;
    v.w = fmaf(v.w, sc, bi); v.w = (v.w >= 0.f) ? v.w : 0.01f*v.w;
    *((float4*)out + i) = v;
}

// ---------------- launch ----------------
extern "C" void kernel_launch(void* const* d_in, const int* in_sizes, int n_in,
                              void* d_out, int out_size) {
    const float* xyz   = (const float*)d_in[0];
    const float* skip  = (const float*)d_in[1];
    const float* xyzp  = (const float*)d_in[2];
    const float* featp = (const float*)d_in[3];
    const float* W1    = (const float*)d_in[4];
    const float* g1    = (const float*)d_in[5];
    const float* b1    = (const float*)d_in[6];
    const float* W2    = (const float*)d_in[7];
    const float* g2    = (const float*)d_in[8];
    const float* b2    = (const float*)d_in[9];
    float* out = (float*)d_out;

    const size_t xyz_elems = (size_t)BB*3*N0;
    const size_t nf_elems  = (size_t)BB*C2f*N0;
    size_t off = 0;
    if ((size_t)out_size >= xyz_elems + nf_elems) {
        cudaMemcpyAsync(out, xyz, xyz_elems*sizeof(float), cudaMemcpyDeviceToDevice);
        off = xyz_elems;
    }

    knn_kernel   <<<dim3(N0/256, BB),          256>>>(xyz, xyzp);
    gemm1a_kernel<<<dim3(NP/128, C1f/128, BB), 512>>>(featp, W1);
    gemm1b_kernel<<<dim3(N0/128, C1f/128, BB), 512>>>(skip, W1);
    stats_reduce <<<C1f, 128>>>(g1, b1, 0);
    gemm2_kernel <<<dim3(N0/128, C2f/128, BB), 512>>>(W2);
    stats_reduce <<<C2f, 128>>>(g2, b2, 1);
    out_kernel   <<<(unsigned)((nf_elems/4 + 255)/256), 256>>>(out + off);
}

// round 5
// speedup vs baseline: 1.6041x; 1.1189x over previous
#include <cuda_runtime.h>
#include <cuda_bf16.h>
#include <cstdint>

#define BB  8
#define N0  8192
#define NP  2048
#define CPf 512
#define CSf 256
#define C1f 256
#define C2f 256
#define KW  768   // CP+CS

// smem row: 64 bf16 hi (128B) | 64 bf16 lo (128B) | pad 16B
#define PITCH 272
#define O_AS   0                 // A tile: 128 x PITCH = 34816
#define O_BS   34816             // B tile: 128 x PITCH
#define SM_BYTES 69632
// epilogue overlays (reuse mainloop smem after final barrier)
#define O_SBUF 0                 // 32 x 132 floats = 16896 B
#define O_SID  16896             // 384 int
#define O_SWT  18432             // 384 float
#define O_CHS  19968             // 128 float
#define O_CHQ  20480             // 128 float

// ---------------- scratch (device globals) ----------------
__device__ int   g_idx[BB*N0*3];
__device__ float g_wt [BB*N0*3];
__device__ float g_Gt [BB*NP*C1f];
__device__ float g_y1 [BB*C1f*N0];
__device__ float g_z  [BB*C2f*N0];
__device__ float g_p1 [C1f*512], g_p2[C1f*512];
__device__ float g_sc1[C1f], g_bi1[C1f], g_sc2[C2f], g_bi2[C2f];

// ---------------- PTX wrappers (baseline ISA, compute_103-safe) ----------------
__device__ __forceinline__ uint32_t smem_u32(const void* p) {
    uint32_t a;
    asm("{ .reg .u64 t; cvta.to.shared.u64 t, %1; cvt.u32.u64 %0, t; }" : "=r"(a) : "l"(p));
    return a;
}
__device__ __forceinline__ void ldm4(uint32_t* r, uint32_t addr) {
    asm volatile("ldmatrix.sync.aligned.m8n8.x4.shared.b16 {%0,%1,%2,%3}, [%4];"
        : "=r"(r[0]), "=r"(r[1]), "=r"(r[2]), "=r"(r[3]) : "r"(addr));
}
__device__ __forceinline__ void mma_bf16(float* d, const uint32_t* a, const uint32_t* b) {
    asm volatile("mma.sync.aligned.m16n8k16.row.col.f32.bf16.bf16.f32 "
        "{%0,%1,%2,%3}, {%4,%5,%6,%7}, {%8,%9}, {%0,%1,%2,%3};"
        : "+f"(d[0]), "+f"(d[1]), "+f"(d[2]), "+f"(d[3])
        : "r"(a[0]), "r"(a[1]), "r"(a[2]), "r"(a[3]), "r"(b[0]), "r"(b[1]));
}
__device__ __forceinline__ uint32_t pack_bf16(float a, float b) {
    __nv_bfloat162 p = __floats2bfloat162_rn(a, b);
    return *(uint32_t*)&p;
}

// ---------------- kNN ----------------
__global__ void knn_kernel(const float* __restrict__ xyz,
                           const float* __restrict__ xyzp) {
    __shared__ float4 sp[NP];
    int b = blockIdx.y;
    const float* p = xyzp + (size_t)b*3*NP;
    for (int j = threadIdx.x; j < NP; j += blockDim.x) {
        float X = p[j], Y = p[NP + j], Z = p[2*NP + j];
        sp[j] = make_float4(X, Y, Z, X*X + Y*Y + Z*Z);
    }
    __syncthreads();
    int n = blockIdx.x*blockDim.x + threadIdx.x;
    const float* q = xyz + (size_t)b*3*N0;
    float qx = q[n], qy = q[N0 + n], qz = q[2*N0 + n];
    float q2 = qx*qx + qy*qy + qz*qz;
    float d0 = 1e30f, d1 = 1e30f, d2 = 1e30f;
    int   i0 = 0, i1 = 0, i2 = 0;
#pragma unroll 4
    for (int j = 0; j < NP; ++j) {
        float4 v = sp[j];
        float dot = qx*v.x + qy*v.y + qz*v.z;
        float d = (q2 + v.w) - 2.0f*dot;
        if (d < d2) {
            if (d < d1) {
                d2 = d1; i2 = i1;
                if (d < d0) { d1 = d0; i1 = i0; d0 = d; i0 = j; }
                else        { d1 = d;  i1 = j; }
            } else { d2 = d; i2 = j; }
        }
    }
    float e0 = 1.0f/(fmaxf(d0, 1e-10f) + 1e-8f);
    float e1 = 1.0f/(fmaxf(d1, 1e-10f) + 1e-8f);
    float e2 = 1.0f/(fmaxf(d2, 1e-10f) + 1e-8f);
    float inv = 1.0f/(e0 + e1 + e2);
    size_t base = ((size_t)b*N0 + n)*3;
    g_idx[base]   = i0; g_idx[base+1] = i1; g_idx[base+2] = i2;
    g_wt [base]   = e0*inv; g_wt[base+1] = e1*inv; g_wt[base+2] = e2*inv;
}

// ===================== bf16x3 mma.sync GEMM core, K-chunk 64, reg-prefetch =====================
// 512 threads, 16 warps (4 n x 4 o), CTA tile 128n x 128o.
// staging map: rs = t&127 (row), cq = t>>7 (k-16-group); 16 values/thread/chunk per operand.
template<bool BN>
__device__ __forceinline__ void gemm_core(char* sm, uint32_t sb,
    const float* __restrict__ A, int ldn, int nb, int kA0,
    const float* __restrict__ W, int ldw, int ob, int kW0,
    int nk64, float acc[2][4][4])
{
    int t = threadIdx.x, lane = t & 31, wid = t >> 5;
    int wn = wid & 3, wo = wid >> 2;
    int rs = t & 127, cq = t >> 7;
    uint32_t aAddr = sb + (uint32_t)(O_AS + (wn*32 + (lane & 15))*PITCH + ((lane >> 4) & 1)*16);
    uint32_t bAddr = sb + (uint32_t)(O_BS + (wo*32 + (lane & 7) + ((lane >> 4) & 1)*8)*PITCH
                                     + ((lane >> 3) & 1)*16);
    float ax[16], bx[16];
    // prefetch chunk 0
    {
        const float* ap = A + (size_t)(kA0 + cq*16)*ldn + nb + rs;
#pragma unroll
        for (int j = 0; j < 16; j++) ax[j] = ap[(size_t)j*ldn];
        const float* wp = W + (size_t)(ob + rs)*ldw + kW0 + cq*16;
#pragma unroll
        for (int j = 0; j < 4; j++) *(float4*)&bx[j*4] = *(const float4*)(wp + j*4);
    }
    for (int it = 0; it < nk64; it++) {
        // ---- convert + store staged chunk ----
        {
            int kA = it*64 + cq*16;   // layer-relative k (BN only used when kA0==0)
            float x[16];
#pragma unroll
            for (int j = 0; j < 16; j++) x[j] = ax[j];
            if (BN) {
#pragma unroll
                for (int j = 0; j < 16; j++) {
                    float v = fmaf(x[j], g_sc1[kA + j], g_bi1[kA + j]);
                    x[j] = (v >= 0.f) ? v : 0.01f*v;
                }
            }
            float lo[16];
#pragma unroll
            for (int j = 0; j < 16; j++) {
                __nv_bfloat16 h = __float2bfloat16(x[j]);
                lo[j] = x[j] - __bfloat162float(h);
            }
            char* arow = sm + O_AS + rs*PITCH + cq*32;
            *(uint4*)arow = make_uint4(pack_bf16(x[0], x[1]),  pack_bf16(x[2], x[3]),
                                       pack_bf16(x[4], x[5]),  pack_bf16(x[6], x[7]));
            *(uint4*)(arow + 16) = make_uint4(pack_bf16(x[8], x[9]),   pack_bf16(x[10], x[11]),
                                              pack_bf16(x[12], x[13]), pack_bf16(x[14], x[15]));
            *(uint4*)(arow + 128) = make_uint4(pack_bf16(lo[0], lo[1]), pack_bf16(lo[2], lo[3]),
                                               pack_bf16(lo[4], lo[5]), pack_bf16(lo[6], lo[7]));
            *(uint4*)(arow + 144) = make_uint4(pack_bf16(lo[8], lo[9]),   pack_bf16(lo[10], lo[11]),
                                               pack_bf16(lo[12], lo[13]), pack_bf16(lo[14], lo[15]));
            float blo[16];
#pragma unroll
            for (int j = 0; j < 16; j++) {
                __nv_bfloat16 h = __float2bfloat16(bx[j]);
                blo[j] = bx[j] - __bfloat162float(h);
            }
            char* brow = sm + O_BS + rs*PITCH + cq*32;
            *(uint4*)brow = make_uint4(pack_bf16(bx[0], bx[1]),  pack_bf16(bx[2], bx[3]),
                                       pack_bf16(bx[4], bx[5]),  pack_bf16(bx[6], bx[7]));
            *(uint4*)(brow + 16) = make_uint4(pack_bf16(bx[8], bx[9]),   pack_bf16(bx[10], bx[11]),
                                              pack_bf16(bx[12], bx[13]), pack_bf16(bx[14], bx[15]));
            *(uint4*)(brow + 128) = make_uint4(pack_bf16(blo[0], blo[1]), pack_bf16(blo[2], blo[3]),
                                               pack_bf16(blo[4], blo[5]), pack_bf16(blo[6], blo[7]));
            *(uint4*)(brow + 144) = make_uint4(pack_bf16(blo[8], blo[9]),   pack_bf16(blo[10], blo[11]),
                                               pack_bf16(blo[12], blo[13]), pack_bf16(blo[14], blo[15]));
        }
        __syncthreads();
        // ---- prefetch next chunk (LDGs overlap the MMA work below) ----
        if (it + 1 < nk64) {
            const float* ap = A + (size_t)(kA0 + (it+1)*64 + cq*16)*ldn + nb + rs;
#pragma unroll
            for (int j = 0; j < 16; j++) ax[j] = ap[(size_t)j*ldn];
            const float* wp = W + (size_t)(ob + rs)*ldw + kW0 + (it+1)*64 + cq*16;
#pragma unroll
            for (int j = 0; j < 4; j++) *(float4*)&bx[j*4] = *(const float4*)(wp + j*4);
        }
        // ---- compute: 4 k16 steps ----
#pragma unroll
        for (int s16 = 0; s16 < 4; s16++) {
            uint32_t Ah[2][4], Al[2][4], Bh[2][4], Bl[2][4];
#pragma unroll
            for (int mt = 0; mt < 2; mt++) {
                uint32_t ad = aAddr + mt*16*PITCH + s16*32;
                ldm4(Ah[mt], ad); ldm4(Al[mt], ad + 128);
            }
#pragma unroll
            for (int np = 0; np < 2; np++) {
                uint32_t bd = bAddr + np*16*PITCH + s16*32;
                ldm4(Bh[np], bd); ldm4(Bl[np], bd + 128);
            }
#pragma unroll
            for (int mt = 0; mt < 2; mt++)
#pragma unroll
            for (int nt = 0; nt < 4; nt++) {
                const uint32_t* bh = &Bh[nt >> 1][(nt & 1)*2];
                const uint32_t* bl = &Bl[nt >> 1][(nt & 1)*2];
                mma_bf16(acc[mt][nt], Ah[mt], bh);
                mma_bf16(acc[mt][nt], Ah[mt], bl);
                mma_bf16(acc[mt][nt], Al[mt], bh);
            }
        }
        __syncthreads();
    }
}

// dump one 32-o strip of accumulators into sbuf[o_local][n]
__device__ __forceinline__ void dump_strip(float* sbuf, int s, float acc[2][4][4]) {
    int t = threadIdx.x, lane = t & 31, wid = t >> 5;
    int wn = wid & 3, wo = wid >> 2;
    if (wo != s) return;
    int g = lane >> 2, c2 = (lane & 3)*2;
#pragma unroll
    for (int mt = 0; mt < 2; mt++)
#pragma unroll
    for (int nt = 0; nt < 4; nt++) {
        int nl = wn*32 + mt*16 + g;
        int ol = nt*8 + c2;
        sbuf[ol*132 + nl]         = acc[mt][nt][0];
        sbuf[(ol+1)*132 + nl]     = acc[mt][nt][1];
        sbuf[ol*132 + nl + 8]     = acc[mt][nt][2];
        sbuf[(ol+1)*132 + nl + 8] = acc[mt][nt][3];
    }
}

// ---------- GEMM 1a: Gt[b][n][o] = W1[:, :512] @ feat ----------
__global__ __launch_bounds__(512, 1)
void gemm1a_kernel(const float* __restrict__ feat, const float* __restrict__ W1) {
    extern __shared__ __align__(16) char sm[];
    uint32_t sb = smem_u32(sm);
    int b = blockIdx.z, nb = blockIdx.x*128, ob = blockIdx.y*128;
    int t = threadIdx.x;
    float acc[2][4][4] = {};
    gemm_core<false>(sm, sb, feat + (size_t)b*CPf*NP, NP, nb, 0,
                     W1, KW, ob, 0, CPf/64, acc);
    float* sbuf = (float*)(sm + O_SBUF);
    int n = t & 127, oq = t >> 7;
    for (int s = 0; s < 4; s++) {
        __syncthreads();
        dump_strip(sbuf, s, acc);
        __syncthreads();
        float f[8];
#pragma unroll
        for (int j = 0; j < 8; j++) f[j] = sbuf[(oq*8 + j)*132 + n];
        float* dst = &g_Gt[((size_t)b*NP + nb + n)*C1f + ob + s*32 + oq*8];
        *(float4*)dst       = make_float4(f[0], f[1], f[2], f[3]);
        *(float4*)(dst + 4) = make_float4(f[4], f[5], f[6], f[7]);
    }
}

// shared epilogue: optional gather, transpose writeout [o][n], BN-stat partials
__device__ __forceinline__ void epi_write(char* sm, float acc[2][4][4],
                                          float* __restrict__ Y, int nb, int ob,
                                          int b, bool gather) {
    int t = threadIdx.x;
    float* sbuf = (float*)(sm + O_SBUF);
    int*   sid  = (int*)(sm + O_SID);
    float* swt  = (float*)(sm + O_SWT);
    float* chs  = (float*)(sm + O_CHS);
    float* chq  = (float*)(sm + O_CHQ);
    if (gather) {
        for (int i = t; i < 384; i += 512) {
            size_t base = ((size_t)b*N0 + nb)*3 + i;
            sid[i] = g_idx[base]; swt[i] = g_wt[base];
        }
    }
    const float* Gt = g_Gt + (size_t)b*NP*C1f;
    for (int s = 0; s < 4; s++) {
        __syncthreads();
        dump_strip(sbuf, s, acc);
        __syncthreads();
        if (gather) {
            int n = t & 127, oq = t >> 7;
            float v[8];
#pragma unroll
            for (int j = 0; j < 8; j++) v[j] = sbuf[(oq*8 + j)*132 + n];
#pragma unroll
            for (int k = 0; k < 3; k++) {
                int   id = sid[n*3 + k];
                float wk = swt[n*3 + k];
                const float* gp = &Gt[(size_t)id*C1f + ob + s*32 + oq*8];
                float4 g0 = *(const float4*)gp;
                float4 g1 = *(const float4*)(gp + 4);
                v[0] = fmaf(wk, g0.x, v[0]); v[1] = fmaf(wk, g0.y, v[1]);
                v[2] = fmaf(wk, g0.z, v[2]); v[3] = fmaf(wk, g0.w, v[3]);
                v[4] = fmaf(wk, g1.x, v[4]); v[5] = fmaf(wk, g1.y, v[5]);
                v[6] = fmaf(wk, g1.z, v[6]); v[7] = fmaf(wk, g1.w, v[7]);
            }
#pragma unroll
            for (int j = 0; j < 8; j++) sbuf[(oq*8 + j)*132 + n] = v[j];
            __syncthreads();
        }
        {
            int ol = t >> 4, seg = t & 15, n = seg*8;
            const float* srow = &sbuf[ol*132 + n];
            float4 x0 = *(const float4*)srow;
            float4 x1 = *(const float4*)(srow + 4);
            float s1 = x0.x + x0.y + x0.z + x0.w + x1.x + x1.y + x1.z + x1.w;
            float s2 = 0.f;
            s2 = fmaf(x0.x, x0.x, s2); s2 = fmaf(x0.y, x0.y, s2);
            s2 = fmaf(x0.z, x0.z, s2); s2 = fmaf(x0.w, x0.w, s2);
            s2 = fmaf(x1.x, x1.x, s2); s2 = fmaf(x1.y, x1.y, s2);
            s2 = fmaf(x1.z, x1.z, s2); s2 = fmaf(x1.w, x1.w, s2);
            float* dst = &Y[(size_t)(ob + s*32 + ol)*N0 + nb + n];
            *(float4*)dst       = x0;
            *(float4*)(dst + 4) = x1;
#pragma unroll
            for (int off = 8; off; off >>= 1) {
                s1 += __shfl_down_sync(0xffffffffu, s1, off, 16);
                s2 += __shfl_down_sync(0xffffffffu, s2, off, 16);
            }
            if (seg == 0) { chs[s*32 + ol] = s1; chq[s*32 + ol] = s2; }
        }
    }
    __syncthreads();
    if (t < 128) {
        int pidx = blockIdx.x + 64*blockIdx.z;
        g_p1[(size_t)(ob + t)*512 + pidx] = chs[t];
        g_p2[(size_t)(ob + t)*512 + pidx] = chq[t];
    }
}

// ---- GEMM 1b: y1 = W1[:, 512:] @ skip + interp(Gt); fused stats ----
__global__ __launch_bounds__(512, 1)
void gemm1b_kernel(const float* __restrict__ skip, const float* __restrict__ W1) {
    extern __shared__ __align__(16) char sm[];
    uint32_t sb = smem_u32(sm);
    int b = blockIdx.z, nb = blockIdx.x*128, ob = blockIdx.y*128;
    float acc[2][4][4] = {};
    gemm_core<false>(sm, sb, skip + (size_t)b*CSf*N0, N0, nb, 0,
                     W1, KW, ob, CPf, CSf/64, acc);
    epi_write(sm, acc, g_y1 + (size_t)b*C1f*N0, nb, ob, b, true);
}

// ---- GEMM 2: z = W2 @ lrelu(BN1(y1)); BN on A-stage; fused stats ----
__global__ __launch_bounds__(512, 1)
void gemm2_kernel(const float* __restrict__ W2) {
    extern __shared__ __align__(16) char sm[];
    uint32_t sb = smem_u32(sm);
    int b = blockIdx.z, nb = blockIdx.x*128, ob = blockIdx.y*128;
    float acc[2][4][4] = {};
    gemm_core<true>(sm, sb, g_y1 + (size_t)b*C1f*N0, N0, nb, 0,
                    W2, C1f, ob, 0, C1f/64, acc);
    epi_write(sm, acc, g_z + (size_t)b*C2f*N0, nb, ob, b, false);
}

// ---------------- stats reduce ----------------
__global__ void stats_reduce(const float* __restrict__ gain,
                             const float* __restrict__ beta, int layer) {
    int o = blockIdx.x, t = threadIdx.x;
    const float* p1 = &g_p1[(size_t)o*512];
    const float* p2 = &g_p2[(size_t)o*512];
    float a = p1[t] + p1[t+128] + p1[t+256] + p1[t+384];
    float c = p2[t] + p2[t+128] + p2[t+256] + p2[t+384];
    __shared__ float r1[128], r2[128];
    r1[t] = a; r2[t] = c; __syncthreads();
    for (int h = 64; h > 0; h >>= 1) {
        if (t < h) { r1[t] += r1[t+h]; r2[t] += r2[t+h]; }
        __syncthreads();
    }
    if (t == 0) {
        const float invN = 1.0f/((float)BB*N0);
        float m   = r1[0]*invN;
        float var = r2[0]*invN - m*m;
        float sc  = gain[o] * (1.0f/sqrtf(var + 1e-3f));
        if (layer) { g_sc2[o] = sc; g_bi2[o] = beta[o] - m*sc; }
        else       { g_sc1[o] = sc; g_bi1[o] = beta[o] - m*sc; }
    }
}

// ---------------- output: lrelu(BN2(z)) ----------------
__global__ void out_kernel(float* __restrict__ out) {
    size_t i = (size_t)blockIdx.x*blockDim.x + threadIdx.x;
    const size_t total4 = (size_t)BB*C2f*N0/4;
    if (i >= total4) return;
    int ch = (int)((i/(N0/4)) % C2f);
    float sc = g_sc2[ch], bi = g_bi2[ch];
    float4 v = *((const float4*)g_z + i);
    v.x = fmaf(v.x, sc, bi); v.x = (v.x >= 0.f) ? v.x : 0.01f*v.x;
    v.y = fmaf(v.y, sc, bi); v.y = (v.y >= 0.f) ? v.y : 0.01f*v.y;
    v.z = fmaf(v.z, sc, bi); v.z = (v.z >= 0.f) ? v.z : 0.01f*v.z;
    v.w = fmaf(v.w, sc, bi); v.w = (v.w >= 0.f) ? v.w : 0.01f*v.w;
    *((float4*)out + i) = v;
}

// ---------------- launch ----------------
extern "C" void kernel_launch(void* const* d_in, const int* in_sizes, int n_in,
                              void* d_out, int out_size) {
    const float* xyz   = (const float*)d_in[0];
    const float* skip  = (const float*)d_in[1];
    const float* xyzp  = (const float*)d_in[2];
    const float* featp = (const float*)d_in[3];
    const float* W1    = (const float*)d_in[4];
    const float* g1    = (const float*)d_in[5];
    const float* b1    = (const float*)d_in[6];
    const float* W2    = (const float*)d_in[7];
    const float* g2    = (const float*)d_in[8];
    const float* b2    = (const float*)d_in[9];
    float* out = (float*)d_out;

    static int s_attr = 0;
    if (!s_attr) {
        cudaFuncSetAttribute(gemm1a_kernel, cudaFuncAttributeMaxDynamicSharedMemorySize, SM_BYTES);
        cudaFuncSetAttribute(gemm1b_kernel, cudaFuncAttributeMaxDynamicSharedMemorySize, SM_BYTES);
        cudaFuncSetAttribute(gemm2_kernel,  cudaFuncAttributeMaxDynamicSharedMemorySize, SM_BYTES);
        s_attr = 1;
    }

    const size_t xyz_elems = (size_t)BB*3*N0;
    const size_t nf_elems  = (size_t)BB*C2f*N0;
    size_t off = 0;
    if ((size_t)out_size >= xyz_elems + nf_elems) {
        cudaMemcpyAsync(out, xyz, xyz_elems*sizeof(float), cudaMemcpyDeviceToDevice);
        off = xyz_elems;
    }

    knn_kernel   <<<dim3(N0/256, BB),          256>>>(xyz, xyzp);
    gemm1a_kernel<<<dim3(NP/128, C1f/128, BB), 512, SM_BYTES>>>(featp, W1);
    gemm1b_kernel<<<dim3(N0/128, C1f/128, BB), 512, SM_BYTES>>>(skip, W1);
    stats_reduce <<<C1f, 128>>>(g1, b1, 0);
    gemm2_kernel <<<dim3(N0/128, C2f/128, BB), 512, SM_BYTES>>>(W2);
    stats_reduce <<<C2f, 128>>>(g2, b2, 1);
    out_kernel   <<<(unsigned)((nf_elems/4 + 255)/256), 256>>>(out + off);
}